// round 11
// baseline (speedup 1.0000x reference)
#include <cuda_runtime.h>
#include <cuda_fp16.h>
#include <cstdint>

#define Bv 4
#define Tv 4096
#define Cv 1024
#define Iv 4096
#define Mv (Bv * Tv)          // 16384 tokens
#define NCHUNK 64
#define CLEN (Tv / NCHUNK)    // 64

typedef unsigned int u32;

// ===========================================================================
// PTX helpers (sm_80-era only — bare compute_103 target rejects tcgen05)
// ===========================================================================
__device__ __forceinline__ u32 smem_to_u32(const void* p) {
    u32 a;
    asm("{ .reg .u64 t; cvta.to.shared.u64 t, %1; cvt.u32.u64 %0, t; }" : "=r"(a) : "l"(p));
    return a;
}
__device__ __forceinline__ void ldsm4(u32* r, u32 addr) {
    asm volatile("ldmatrix.sync.aligned.m8n8.x4.shared.b16 {%0,%1,%2,%3}, [%4];"
                 : "=r"(r[0]), "=r"(r[1]), "=r"(r[2]), "=r"(r[3]) : "r"(addr));
}
__device__ __forceinline__ void mma16816(float* c, const u32* a, const u32* b) {
    asm volatile("mma.sync.aligned.m16n8k16.row.col.f32.f16.f16.f32 "
                 "{%0,%1,%2,%3}, {%4,%5,%6,%7}, {%8,%9}, {%0,%1,%2,%3};"
                 : "+f"(c[0]), "+f"(c[1]), "+f"(c[2]), "+f"(c[3])
                 : "r"(a[0]), "r"(a[1]), "r"(a[2]), "r"(a[3]), "r"(b[0]), "r"(b[1]));
}
__device__ __forceinline__ void cpasync16(u32 s, const void* g) {
    asm volatile("cp.async.cg.shared.global [%0], [%1], 16;" :: "r"(s), "l"(g));
}
__device__ __forceinline__ void cpasync_commit() { asm volatile("cp.async.commit_group;" ::: "memory"); }
template<int N> __device__ __forceinline__ void cpasync_wait() {
    asm volatile("cp.async.wait_group %0;" :: "n"(N) : "memory");
}

// ===========================================================================
// Scratch (__device__ globals; allocation-free)
// ===========================================================================
__device__ float g_ek [(size_t)Mv * Cv];      // exp(clip(k)) — written by k-GEMM epilogue
__device__ float g_v  [(size_t)Mv * Cv];
__device__ float g_r  [(size_t)Mv * Cv];
__device__ float g_x1 [(size_t)Mv * Cv];
__device__ float g_r2 [(size_t)Mv * Cv];
__device__ float g_sA [Bv * NCHUNK * Cv];
__device__ float g_sB [Bv * NCHUNK * Cv];

__device__ __half a_xk_h[(size_t)Mv * Cv];
__device__ __half a_xv_h[(size_t)Mv * Cv];
__device__ __half a_xr_h[(size_t)Mv * Cv];
__device__ __half a_rw_h[(size_t)Mv * Cv];
__device__ __half a_k2_h[(size_t)Mv * Iv];

// weights transposed to [N,K] K-major fp16
__device__ __half w_k_h [Cv * Cv];
__device__ __half w_v_h [Cv * Cv];
__device__ __half w_r_h [Cv * Cv];
__device__ __half w_o_h [Cv * Cv];
__device__ __half w_r2_h[Cv * Cv];
__device__ __half w_k2_h[(size_t)Iv * Cv];
__device__ __half w_v2_h[(size_t)Cv * Iv];

// ===========================================================================
// Numeric helpers
// ===========================================================================
#define EXP20F 4.851652e8f
__device__ __forceinline__ float clip20(float x) { return fminf(fmaxf(x, -20.f), 20.f); }
__device__ __forceinline__ float sigm(float x)   { return 1.0f / (1.0f + __expf(-x)); }

__device__ __forceinline__ u32 pack2h(float a, float b) {
    __half ha = __float2half_rn(a), hb = __float2half_rn(b);
    return (u32)(*(uint16_t*)&ha) | ((u32)(*(uint16_t*)&hb) << 16);
}
__device__ __forceinline__ void round4st(float4 v, __half* Hi, size_t e) {
    *reinterpret_cast<uint2*>(Hi + e) = make_uint2(pack2h(v.x, v.y), pack2h(v.z, v.w));
}
__device__ __forceinline__ float4 mixf4(float4 m, float4 h, float4 s) {
    float4 o;
    o.x = m.x * h.x + (1.f - m.x) * s.x;
    o.y = m.y * h.y + (1.f - m.y) * s.y;
    o.z = m.z * h.z + (1.f - m.z) * s.z;
    o.w = m.w * h.w + (1.f - m.w) * s.w;
    return o;
}

// ===========================================================================
// Fused RMSNorm + token-shift mix
// ===========================================================================
__device__ __forceinline__ void norm2_reduce(float sc, float sp, float& oc, float& op) {
#pragma unroll
    for (int o = 16; o > 0; o >>= 1) {
        sc += __shfl_xor_sync(0xffffffffu, sc, o);
        sp += __shfl_xor_sync(0xffffffffu, sp, o);
    }
    __shared__ float rc[8], rp[8];
    const int tid = threadIdx.x;
    if ((tid & 31) == 0) { rc[tid >> 5] = sc; rp[tid >> 5] = sp; }
    __syncthreads();
    float tc = 0.f, tp = 0.f;
#pragma unroll
    for (int i = 0; i < 8; i++) { tc += rc[i]; tp += rp[i]; }
    oc = rsqrtf(tc * (1.0f / (float)Cv) + 1e-6f);
    op = rsqrtf(tp * (1.0f / (float)Cv) + 1e-6f);
}

__global__ void __launch_bounds__(256) fusedmix3_kernel(const float* __restrict__ x,
    const float* __restrict__ w,
    const float* __restrict__ mk, const float* __restrict__ mv, const float* __restrict__ mr,
    __half* kh, __half* vh, __half* rh)
{
    const int row = blockIdx.x, tid = threadIdx.x;
    const int t = row & (Tv - 1);
    const size_t i4 = (size_t)row * (Cv / 4) + tid;
    float4 xc = reinterpret_cast<const float4*>(x)[i4];
    float4 xp = make_float4(0.f, 0.f, 0.f, 0.f);
    if (t != 0) xp = reinterpret_cast<const float4*>(x)[i4 - (Cv / 4)];
    float sc, sp;
    norm2_reduce(xc.x*xc.x + xc.y*xc.y + xc.z*xc.z + xc.w*xc.w,
                 xp.x*xp.x + xp.y*xp.y + xp.z*xp.z + xp.w*xp.w, sc, sp);
    float4 wv = reinterpret_cast<const float4*>(w)[tid];
    float4 hv = make_float4(xc.x*sc*wv.x, xc.y*sc*wv.y, xc.z*sc*wv.z, xc.w*sc*wv.w);
    float4 sh = make_float4(xp.x*sp*wv.x, xp.y*sp*wv.y, xp.z*sp*wv.z, xp.w*sp*wv.w);
    const size_t e = i4 * 4;
    round4st(mixf4(reinterpret_cast<const float4*>(mk)[tid], hv, sh), kh, e);
    round4st(mixf4(reinterpret_cast<const float4*>(mv)[tid], hv, sh), vh, e);
    round4st(mixf4(reinterpret_cast<const float4*>(mr)[tid], hv, sh), rh, e);
}

__global__ void __launch_bounds__(256) fusedmix2_kernel(const float* __restrict__ x,
    const float* __restrict__ w,
    const float* __restrict__ mk, const float* __restrict__ mr,
    __half* kh, __half* rh)
{
    const int row = blockIdx.x, tid = threadIdx.x;
    const int t = row & (Tv - 1);
    const size_t i4 = (size_t)row * (Cv / 4) + tid;
    float4 xc = reinterpret_cast<const float4*>(x)[i4];
    float4 xp = make_float4(0.f, 0.f, 0.f, 0.f);
    if (t != 0) xp = reinterpret_cast<const float4*>(x)[i4 - (Cv / 4)];
    float sc, sp;
    norm2_reduce(xc.x*xc.x + xc.y*xc.y + xc.z*xc.z + xc.w*xc.w,
                 xp.x*xp.x + xp.y*xp.y + xp.z*xp.z + xp.w*xp.w, sc, sp);
    float4 wv = reinterpret_cast<const float4*>(w)[tid];
    float4 hv = make_float4(xc.x*sc*wv.x, xc.y*sc*wv.y, xc.z*sc*wv.z, xc.w*sc*wv.w);
    float4 sh = make_float4(xp.x*sp*wv.x, xp.y*sp*wv.y, xp.z*sp*wv.z, xp.w*sp*wv.w);
    const size_t e = i4 * 4;
    round4st(mixf4(reinterpret_cast<const float4*>(mk)[tid], hv, sh), kh, e);
    round4st(mixf4(reinterpret_cast<const float4*>(mr)[tid], hv, sh), rh, e);
}

// ===========================================================================
// Weight transpose: W[K,N] fp32 -> [N,K] fp16, 64x64 tiles, vectorized I/O
//   load: float4 along N; store: 8 packed halves (16B) along K
// ===========================================================================
__device__ __forceinline__ void wtrans_body(const float* W, __half* D, int K, int N) {
    __shared__ float t[64][69];
    const int tid = threadIdx.x;
    const int n0 = blockIdx.x * 64, k0 = blockIdx.y * 64;
    const int lk = tid >> 4, ln4 = (tid & 15) * 4;
#pragma unroll
    for (int r = 0; r < 4; r++) {
        const int krow = r * 16 + lk;
        const float4 vv = *reinterpret_cast<const float4*>(&W[(size_t)(k0 + krow) * N + n0 + ln4]);
        t[krow][ln4 + 0] = vv.x; t[krow][ln4 + 1] = vv.y;
        t[krow][ln4 + 2] = vv.z; t[krow][ln4 + 3] = vv.w;
    }
    __syncthreads();
#pragma unroll
    for (int u = 0; u < 2; u++) {
        const int unit = tid * 2 + u;
        const int n = unit >> 3, kc = (unit & 7) * 8;
        u32 p[4];
#pragma unroll
        for (int q = 0; q < 4; q++)
            p[q] = pack2h(t[kc + 2*q][n], t[kc + 2*q + 1][n]);
        *reinterpret_cast<uint4*>(&D[(size_t)(n0 + n) * K + k0 + kc]) =
            make_uint4(p[0], p[1], p[2], p[3]);
    }
}

__global__ void __launch_bounds__(256) wsplit5_kernel(
    const float* s0, const float* s1, const float* s2, const float* s3, const float* s4,
    __half* d0, __half* d1, __half* d2, __half* d3, __half* d4)
{
    const float* S; __half* D;
    switch (blockIdx.z) {
        case 0: S = s0; D = d0; break;
        case 1: S = s1; D = d1; break;
        case 2: S = s2; D = d2; break;
        case 3: S = s3; D = d3; break;
        default: S = s4; D = d4; break;
    }
    wtrans_body(S, D, Cv, Cv);
}

__global__ void __launch_bounds__(256) wsplit_kernel(const float* __restrict__ W,
    __half* __restrict__ D, int K, int N)
{
    wtrans_body(W, D, K, N);
}

// ===========================================================================
// WKV scan — exp-free (reads ek = exp(clip(k)) precomputed by k-GEMM epilogue)
// ===========================================================================
__global__ void __launch_bounds__(1024) wkv_pass1(const float* __restrict__ ek,
    const float* __restrict__ v, const float* __restrict__ td,
    float* __restrict__ sA, float* __restrict__ sB)
{
    const int c = threadIdx.x, chunk = blockIdx.x, b = blockIdx.y;
    const float ew = __expf(clip20(-__expf(td[c])));
    float a = 0.f, bb = 0.f;
    size_t base = ((size_t)(b * Tv) + (size_t)chunk * CLEN) * Cv + c;
    for (int t = 0; t < CLEN; t++) {
        const size_t ix = base + (size_t)t * Cv;
        const float e = ek[ix];
        a = ew * a + e * v[ix];  bb = ew * bb + e;
    }
    const int sidx = (b * NCHUNK + chunk) * Cv + c;
    sA[sidx] = a; sB[sidx] = bb;
}

__global__ void __launch_bounds__(1024) wkv_pass2(const float* __restrict__ td,
                                                  float* __restrict__ sA, float* __restrict__ sB)
{
    const int c = threadIdx.x, b = blockIdx.x;
    const float w = clip20(-__expf(td[c]));
    const float ewL = __expf(w * (float)CLEN);
    float Sa = 0.f, Sb = 0.f;
    for (int i = 0; i < NCHUNK; i++) {
        const int idx = (b * NCHUNK + i) * Cv + c;
        const float la = sA[idx], lb = sB[idx];
        sA[idx] = Sa; sB[idx] = Sb;
        Sa = ewL * Sa + la;  Sb = ewL * Sb + lb;
    }
}

__global__ void __launch_bounds__(1024) wkv_pass3(const float* __restrict__ ek,
    const float* __restrict__ v, const float* __restrict__ r,
    const float* __restrict__ td, const float* __restrict__ tf,
    const float* __restrict__ sA, const float* __restrict__ sB,
    __half* __restrict__ oh)
{
    const int c = threadIdx.x, chunk = blockIdx.x, b = blockIdx.y;
    const float ew = __expf(clip20(-__expf(td[c])));
    const float eu = __expf(tf[c]);
    const int sidx = (b * NCHUNK + chunk) * Cv + c;
    float a = sA[sidx], bb = sB[sidx];
    size_t base = ((size_t)(b * Tv) + (size_t)chunk * CLEN) * Cv + c;
    for (int t = 0; t < CLEN; t++) {
        const size_t ix = base + (size_t)t * Cv;
        const float e = ek[ix], vt = v[ix];
        const float ekt = fminf(eu * e, EXP20F);   // = exp(clip(u+k)); clip inactive for |k|<~6
        const float o = r[ix] * __fdividef(a + ekt * vt, bb + ekt + 1e-8f);
        oh[ix] = __float2half_rn(o);
        a = ew * a + e * vt;  bb = ew * bb + e;
    }
}

// ===========================================================================
// HMMA fp16 GEMM core v2: block 128x256, warp tile 64x64 (8 warps, 2m x 4n),
// Kchunk=64, 3-stage cp.async. Higher MAC/LDSM-byte to beat the smem crossbar
// bound (prev: 192KB LDSM per 1.05M MAC; now: 256KB per 2.1M MAC).
// D = A[M,K] @ B^T (B stored [N,K] K-major).
// ===========================================================================
#define STAGE_B 49152                 // A: 16KB (128 rows x 128B) + B: 32KB (256 rows x 128B)
#define GSMEM   (3 * STAGE_B)

__device__ __forceinline__ u32 swz(u32 o) { return o ^ ((o >> 3) & 0x70); }

template<int KDIM>
__device__ __forceinline__ void gemm_core(const __half* Abase, const __half* Bbase,
                                          int arow0, int brow0, char* smem,
                                          float acc[4][8][4])
{
    const u32 sbase = smem_to_u32(smem);
    const int tid = threadIdx.x, wid = tid >> 5, lane = tid & 31;

    // ---- loaders: A 2 threads/row (4x16B each); B 1 thread/row (8x16B)
    const int arow = tid >> 1;
    const int asegb = (tid & 1) * 64;
    u32 soffA[4], soffB[8];
#pragma unroll
    for (int j = 0; j < 4; j++) soffA[j] = swz((u32)(arow * 128 + asegb + j * 16));
#pragma unroll
    for (int j = 0; j < 8; j++) soffB[j] = 16384u + swz((u32)(tid * 128 + j * 16));
    const char* gA = (const char*)(Abase + (size_t)(arow0 + arow) * KDIM) + asegb;
    const char* gB = (const char*)(Bbase + (size_t)(brow0 + tid) * KDIM);

    auto ld_chunk = [&](int stage, int c) {
        const u32 sb = sbase + stage * STAGE_B;
        const size_t go = (size_t)c * 128;
#pragma unroll
        for (int j = 0; j < 4; j++) cpasync16(sb + soffA[j], gA + go + j * 16);
#pragma unroll
        for (int j = 0; j < 8; j++) cpasync16(sb + soffB[j], gB + go + j * 16);
        cpasync_commit();
    };

    // ---- warp tiling: 2(m) x 4(n) of 64x64
    const int wm = (wid & 1) * 64;
    const int wn = (wid >> 1) * 64;
    const int laneA_row = lane & 15;
    const int laneA_kb  = (lane >> 4) * 16;
    const int laneB_row = (lane & 7) | (((lane >> 4) & 1) << 3);
    const int laneB_kb  = ((lane >> 3) & 1) * 16;

#pragma unroll
    for (int i = 0; i < 4; i++)
#pragma unroll
        for (int j = 0; j < 8; j++)
#pragma unroll
            for (int q = 0; q < 4; q++) acc[i][j][q] = 0.f;

    constexpr int nch = KDIM >> 6;
    ld_chunk(0, 0); ld_chunk(1, 1); ld_chunk(2, 2);

    for (int c = 0; c < nch; ++c) {
        if      (c + 2 < nch) cpasync_wait<2>();
        else if (c + 1 < nch) cpasync_wait<1>();
        else                  cpasync_wait<0>();
        __syncthreads();

        const u32 sb = sbase + (c % 3) * STAGE_B;
#pragma unroll
        for (int ks = 0; ks < 4; ++ks) {
            const int kb = ks * 32;
            u32 ah[4][4], bh[4][4];
#pragma unroll
            for (int i = 0; i < 4; i++)
                ldsm4(ah[i], sb + swz((u32)((wm + 16 * i + laneA_row) * 128 + kb + laneA_kb)));
#pragma unroll
            for (int g = 0; g < 4; g++)
                ldsm4(bh[g], sb + 16384u + swz((u32)((wn + 16 * g + laneB_row) * 128 + kb + laneB_kb)));
#pragma unroll
            for (int i = 0; i < 4; i++)
#pragma unroll
                for (int j = 0; j < 8; j++)
                    mma16816(acc[i][j], ah[i], &bh[j >> 1][(j & 1) * 2]);
        }
        __syncthreads();
        if (c + 3 < nch) ld_chunk(c % 3, c + 3);
    }
}

// epilogue addressing: frag (i,j) -> rows bm+wm+16i+{gid,gid+8}, cols bn+wn+8j+2tg
#define EPI_SETUP() \
    const int wid = threadIdx.x >> 5, lane = threadIdx.x & 31; \
    const int wm = (wid & 1) * 64, wn = (wid >> 1) * 64; \
    const int gid = lane >> 2, tg = lane & 3;

// ---- fused k/v/r GEMM: grid (12, 128); x in [0,4)=k->exp, [4,8)=v, [8,12)=r->sigm
__global__ void __launch_bounds__(256, 1) hgemm_kvr(
    const __half* __restrict__ A0, const __half* __restrict__ A1, const __half* __restrict__ A2,
    const __half* __restrict__ B0, const __half* __restrict__ B1, const __half* __restrict__ B2,
    float* __restrict__ C0, float* __restrict__ C1, float* __restrict__ C2)
{
    extern __shared__ __align__(1024) char smem[];
    const int sel = blockIdx.x >> 2;
    const int bxe = blockIdx.x & 3;
    const __half* A = (sel == 0) ? A0 : ((sel == 1) ? A1 : A2);
    const __half* B = (sel == 0) ? B0 : ((sel == 1) ? B1 : B2);
    float*       C = (sel == 0) ? C0 : ((sel == 1) ? C1 : C2);

    float acc[4][8][4];
    gemm_core<Cv>(A, B, blockIdx.y * 128, bxe * 256, smem, acc);

    EPI_SETUP();
    const int bm = blockIdx.y * 128, bn = bxe * 256;
#pragma unroll
    for (int i = 0; i < 4; i++) {
        const int r0 = bm + wm + 16 * i + gid;
#pragma unroll
        for (int j = 0; j < 8; j++) {
            const int cc = bn + wn + 8 * j + 2 * tg;
            const size_t idx0 = (size_t)r0 * Cv + cc;
            const size_t idx1 = idx0 + (size_t)8 * Cv;
            float v0 = acc[i][j][0], v1 = acc[i][j][1];
            float v2 = acc[i][j][2], v3 = acc[i][j][3];
            if (sel == 0) {
                v0 = __expf(clip20(v0)); v1 = __expf(clip20(v1));
                v2 = __expf(clip20(v2)); v3 = __expf(clip20(v3));
            } else if (sel == 2) {
                v0 = sigm(v0); v1 = sigm(v1); v2 = sigm(v2); v3 = sigm(v3);
            }
            *reinterpret_cast<float2*>(&C[idx0]) = make_float2(v0, v1);
            *reinterpret_cast<float2*>(&C[idx1]) = make_float2(v2, v3);
        }
    }
}

// ---- Wo GEMM: x1 = x + rw@Wo^T; grid (4, 128)
__global__ void __launch_bounds__(256, 1) hgemm_add(
    const __half* __restrict__ A, const __half* __restrict__ B,
    float* __restrict__ C, const float* __restrict__ E)
{
    extern __shared__ __align__(1024) char smem[];
    float acc[4][8][4];
    gemm_core<Cv>(A, B, blockIdx.y * 128, blockIdx.x * 256, smem, acc);

    EPI_SETUP();
    const int bm = blockIdx.y * 128, bn = blockIdx.x * 256;
#pragma unroll
    for (int i = 0; i < 4; i++) {
        const int r0 = bm + wm + 16 * i + gid;
#pragma unroll
        for (int j = 0; j < 8; j++) {
            const int cc = bn + wn + 8 * j + 2 * tg;
            const size_t idx0 = (size_t)r0 * Cv + cc;
            const size_t idx1 = idx0 + (size_t)8 * Cv;
            const float2 e0 = *reinterpret_cast<const float2*>(&E[idx0]);
            const float2 e1 = *reinterpret_cast<const float2*>(&E[idx1]);
            *reinterpret_cast<float2*>(&C[idx0]) = make_float2(acc[i][j][0] + e0.x, acc[i][j][1] + e0.y);
            *reinterpret_cast<float2*>(&C[idx1]) = make_float2(acc[i][j][2] + e1.x, acc[i][j][3] + e1.y);
        }
    }
}

// ---- fused k2/r2 GEMM: grid (20, 128); x<16: k2=relu^2 (fp16, N=Iv); x>=16: r2=sigm (fp32, N=Cv)
__global__ void __launch_bounds__(256, 1) hgemm_k2r2(
    const __half* __restrict__ A0, const __half* __restrict__ A1,
    const __half* __restrict__ B0, const __half* __restrict__ B1,
    __half* __restrict__ C0, float* __restrict__ C1)
{
    extern __shared__ __align__(1024) char smem[];
    const bool isr2 = (blockIdx.x >= 16);
    const int bxe = isr2 ? (blockIdx.x - 16) : blockIdx.x;
    const __half* A = isr2 ? A1 : A0;
    const __half* B = isr2 ? B1 : B0;

    float acc[4][8][4];
    gemm_core<Cv>(A, B, blockIdx.y * 128, bxe * 256, smem, acc);

    EPI_SETUP();
    const int bm = blockIdx.y * 128, bn = bxe * 256;
    const int N = isr2 ? Cv : Iv;
#pragma unroll
    for (int i = 0; i < 4; i++) {
        const int r0 = bm + wm + 16 * i + gid;
#pragma unroll
        for (int j = 0; j < 8; j++) {
            const int cc = bn + wn + 8 * j + 2 * tg;
            const size_t idx0 = (size_t)r0 * N + cc;
            const size_t idx1 = idx0 + (size_t)8 * N;
            float v0 = acc[i][j][0], v1 = acc[i][j][1];
            float v2 = acc[i][j][2], v3 = acc[i][j][3];
            if (!isr2) {
                v0 = fmaxf(v0, 0.f); v0 *= v0;  v1 = fmaxf(v1, 0.f); v1 *= v1;
                v2 = fmaxf(v2, 0.f); v2 *= v2;  v3 = fmaxf(v3, 0.f); v3 *= v3;
                *reinterpret_cast<u32*>(C0 + idx0) = pack2h(v0, v1);
                *reinterpret_cast<u32*>(C0 + idx1) = pack2h(v2, v3);
            } else {
                *reinterpret_cast<float2*>(&C1[idx0]) = make_float2(sigm(v0), sigm(v1));
                *reinterpret_cast<float2*>(&C1[idx1]) = make_float2(sigm(v2), sigm(v3));
            }
        }
    }
}

// ---- v2 GEMM (K=Iv): out = x1 + r2 * (k2@Wv2^T); grid (4, 128)
__global__ void __launch_bounds__(256, 1) hgemm_muladd(
    const __half* __restrict__ A, const __half* __restrict__ B,
    float* __restrict__ C, const float* __restrict__ E1, const float* __restrict__ E2)
{
    extern __shared__ __align__(1024) char smem[];
    float acc[4][8][4];
    gemm_core<Iv>(A, B, blockIdx.y * 128, blockIdx.x * 256, smem, acc);

    EPI_SETUP();
    const int bm = blockIdx.y * 128, bn = blockIdx.x * 256;
#pragma unroll
    for (int i = 0; i < 4; i++) {
        const int r0 = bm + wm + 16 * i + gid;
#pragma unroll
        for (int j = 0; j < 8; j++) {
            const int cc = bn + wn + 8 * j + 2 * tg;
            const size_t idx0 = (size_t)r0 * Cv + cc;
            const size_t idx1 = idx0 + (size_t)8 * Cv;
            const float2 a0 = *reinterpret_cast<const float2*>(&E1[idx0]);
            const float2 a1 = *reinterpret_cast<const float2*>(&E1[idx1]);
            const float2 m0 = *reinterpret_cast<const float2*>(&E2[idx0]);
            const float2 m1 = *reinterpret_cast<const float2*>(&E2[idx1]);
            *reinterpret_cast<float2*>(&C[idx0]) =
                make_float2(a0.x + m0.x * acc[i][j][0], a0.y + m0.y * acc[i][j][1]);
            *reinterpret_cast<float2*>(&C[idx1]) =
                make_float2(a1.x + m1.x * acc[i][j][2], a1.y + m1.y * acc[i][j][3]);
        }
    }
}

// ===========================================================================
// Launch
// ===========================================================================
extern "C" void kernel_launch(void* const* d_in, const int* in_sizes, int n_in,
                              void* d_out, int out_size)
{
    const float* x     = (const float*)d_in[0];
    const float* ln1_w = (const float*)d_in[1];
    const float* ln2_w = (const float*)d_in[2];
    const float* td    = (const float*)d_in[3];
    const float* tf    = (const float*)d_in[4];
    const float* mk    = (const float*)d_in[5];
    const float* mv    = (const float*)d_in[6];
    const float* mr    = (const float*)d_in[7];
    const float* Wk    = (const float*)d_in[8];
    const float* Wv    = (const float*)d_in[9];
    const float* Wr    = (const float*)d_in[10];
    const float* Wo    = (const float*)d_in[11];
    const float* mk2   = (const float*)d_in[12];
    const float* mr2   = (const float*)d_in[13];
    const float* Wk2   = (const float*)d_in[14];
    const float* Wv2   = (const float*)d_in[15];
    const float* Wr2   = (const float*)d_in[16];
    float* out = (float*)d_out;

#define SYM(p, s) void* p##_; cudaGetSymbolAddress(&p##_, s); auto* p = (decltype(&s[0]))p##_
    SYM(ek,  g_ek); SYM(v,   g_v);  SYM(r,   g_r);
    SYM(x1,  g_x1); SYM(r2,  g_r2); SYM(sA,  g_sA); SYM(sB,  g_sB);
    SYM(xkh, a_xk_h); SYM(xvh, a_xv_h); SYM(xrh, a_xr_h);
    SYM(rwh, a_rw_h); SYM(k2h, a_k2_h);
    SYM(wkh, w_k_h);  SYM(wvh, w_v_h);  SYM(wrh, w_r_h);  SYM(woh, w_o_h);
    SYM(wr2h, w_r2_h); SYM(wk2h, w_k2_h); SYM(wv2h, w_v2_h);
#undef SYM

    cudaFuncSetAttribute(hgemm_kvr,    cudaFuncAttributeMaxDynamicSharedMemorySize, GSMEM);
    cudaFuncSetAttribute(hgemm_add,    cudaFuncAttributeMaxDynamicSharedMemorySize, GSMEM);
    cudaFuncSetAttribute(hgemm_k2r2,   cudaFuncAttributeMaxDynamicSharedMemorySize, GSMEM);
    cudaFuncSetAttribute(hgemm_muladd, cudaFuncAttributeMaxDynamicSharedMemorySize, GSMEM);

    // weight transposes (64x64 tiles, vectorized)
    wsplit5_kernel<<<dim3(Cv/64, Cv/64, 5), 256>>>(Wk, Wv, Wr, Wo, Wr2,
                                                   wkh, wvh, wrh, woh, wr2h);
    wsplit_kernel<<<dim3(Iv/64, Cv/64), 256>>>(Wk2, wk2h, Cv, Iv);  // [C,I] -> [I,C]
    wsplit_kernel<<<dim3(Cv/64, Iv/64), 256>>>(Wv2, wv2h, Iv, Cv);  // [I,C] -> [C,I]

    // --- time mixing ---
    fusedmix3_kernel<<<Mv, 256>>>(x, ln1_w, mk, mv, mr, xkh, xvh, xrh);
    hgemm_kvr<<<dim3(12, 128), 256, GSMEM>>>(xkh, xvh, xrh, wkh, wvh, wrh, ek, v, r);
    wkv_pass1<<<dim3(NCHUNK, Bv), Cv>>>(ek, v, td, sA, sB);
    wkv_pass2<<<Bv, Cv>>>(td, sA, sB);
    wkv_pass3<<<dim3(NCHUNK, Bv), Cv>>>(ek, v, r, td, tf, sA, sB, rwh);
    hgemm_add<<<dim3(4, 128), 256, GSMEM>>>(rwh, woh, x1, x);

    // --- channel mixing ---
    fusedmix2_kernel<<<Mv, 256>>>(x1, ln2_w, mk2, mr2, xkh, xrh);
    hgemm_k2r2<<<dim3(20, 128), 256, GSMEM>>>(xkh, xrh, wk2h, wr2h, k2h, r2);
    hgemm_muladd<<<dim3(4, 128), 256, GSMEM>>>(k2h, wv2h, out, x1, r2);
}

// round 14
// speedup vs baseline: 1.3501x; 1.3501x over previous
#include <cuda_runtime.h>
#include <cuda_fp16.h>
#include <cstdint>

#define Bv 4
#define Tv 4096
#define Cv 1024
#define Iv 4096
#define Mv (Bv * Tv)          // 16384 tokens
#define NCHUNK 64
#define CLEN (Tv / NCHUNK)    // 64

typedef unsigned int u32;

// ===========================================================================
// PTX helpers (sm_80-era only — bare compute_103 target rejects tcgen05)
// ===========================================================================
__device__ __forceinline__ u32 smem_to_u32(const void* p) {
    u32 a;
    asm("{ .reg .u64 t; cvta.to.shared.u64 t, %1; cvt.u32.u64 %0, t; }" : "=r"(a) : "l"(p));
    return a;
}
__device__ __forceinline__ void ldsm4(u32* r, u32 addr) {
    asm volatile("ldmatrix.sync.aligned.m8n8.x4.shared.b16 {%0,%1,%2,%3}, [%4];"
                 : "=r"(r[0]), "=r"(r[1]), "=r"(r[2]), "=r"(r[3]) : "r"(addr));
}
__device__ __forceinline__ void mma16816(float* c, const u32* a, const u32* b) {
    asm volatile("mma.sync.aligned.m16n8k16.row.col.f32.f16.f16.f32 "
                 "{%0,%1,%2,%3}, {%4,%5,%6,%7}, {%8,%9}, {%0,%1,%2,%3};"
                 : "+f"(c[0]), "+f"(c[1]), "+f"(c[2]), "+f"(c[3])
                 : "r"(a[0]), "r"(a[1]), "r"(a[2]), "r"(a[3]), "r"(b[0]), "r"(b[1]));
}
__device__ __forceinline__ void cpasync16(u32 s, const void* g) {
    asm volatile("cp.async.cg.shared.global [%0], [%1], 16;" :: "r"(s), "l"(g));
}
__device__ __forceinline__ void cpasync_commit() { asm volatile("cp.async.commit_group;" ::: "memory"); }
template<int N> __device__ __forceinline__ void cpasync_wait() {
    asm volatile("cp.async.wait_group %0;" :: "n"(N) : "memory");
}

// ===========================================================================
// Scratch (__device__ globals; allocation-free)
// ===========================================================================
__device__ __half g_ek [(size_t)Mv * Cv];     // exp(clip(k)) fp16 — k-GEMM epilogue
__device__ __half g_v  [(size_t)Mv * Cv];     // fp16
__device__ __half g_r  [(size_t)Mv * Cv];     // fp16 sigmoid
__device__ float  g_x1 [(size_t)Mv * Cv];
__device__ float  g_r2 [(size_t)Mv * Cv];
__device__ float  g_sA [Bv * NCHUNK * Cv];
__device__ float  g_sB [Bv * NCHUNK * Cv];

__device__ __half a_xk_h[(size_t)Mv * Cv];
__device__ __half a_xv_h[(size_t)Mv * Cv];
__device__ __half a_xr_h[(size_t)Mv * Cv];
__device__ __half a_rw_h[(size_t)Mv * Cv];
__device__ __half a_k2_h[(size_t)Mv * Iv];

// weights transposed to [N,K] K-major fp16
__device__ __half w_k_h [Cv * Cv];
__device__ __half w_v_h [Cv * Cv];
__device__ __half w_r_h [Cv * Cv];
__device__ __half w_o_h [Cv * Cv];
__device__ __half w_r2_h[Cv * Cv];
__device__ __half w_k2_h[(size_t)Iv * Cv];
__device__ __half w_v2_h[(size_t)Cv * Iv];

// ===========================================================================
// Numeric helpers
// ===========================================================================
#define EXP20F 4.851652e8f
__device__ __forceinline__ float clip20(float x) { return fminf(fmaxf(x, -20.f), 20.f); }
__device__ __forceinline__ float sigm(float x)   { return 1.0f / (1.0f + __expf(-x)); }

__device__ __forceinline__ u32 pack2h(float a, float b) {
    __half ha = __float2half_rn(a), hb = __float2half_rn(b);
    return (u32)(*(uint16_t*)&ha) | ((u32)(*(uint16_t*)&hb) << 16);
}
__device__ __forceinline__ void round4st(float4 v, __half* Hi, size_t e) {
    *reinterpret_cast<uint2*>(Hi + e) = make_uint2(pack2h(v.x, v.y), pack2h(v.z, v.w));
}
__device__ __forceinline__ float4 mixf4(float4 m, float4 h, float4 s) {
    float4 o;
    o.x = m.x * h.x + (1.f - m.x) * s.x;
    o.y = m.y * h.y + (1.f - m.y) * s.y;
    o.z = m.z * h.z + (1.f - m.z) * s.z;
    o.w = m.w * h.w + (1.f - m.w) * s.w;
    return o;
}

// ===========================================================================
// Fused RMSNorm + token-shift mix
// ===========================================================================
__device__ __forceinline__ void norm2_reduce(float sc, float sp, float& oc, float& op) {
#pragma unroll
    for (int o = 16; o > 0; o >>= 1) {
        sc += __shfl_xor_sync(0xffffffffu, sc, o);
        sp += __shfl_xor_sync(0xffffffffu, sp, o);
    }
    __shared__ float rc[8], rp[8];
    const int tid = threadIdx.x;
    if ((tid & 31) == 0) { rc[tid >> 5] = sc; rp[tid >> 5] = sp; }
    __syncthreads();
    float tc = 0.f, tp = 0.f;
#pragma unroll
    for (int i = 0; i < 8; i++) { tc += rc[i]; tp += rp[i]; }
    oc = rsqrtf(tc * (1.0f / (float)Cv) + 1e-6f);
    op = rsqrtf(tp * (1.0f / (float)Cv) + 1e-6f);
}

__global__ void __launch_bounds__(256) fusedmix3_kernel(const float* __restrict__ x,
    const float* __restrict__ w,
    const float* __restrict__ mk, const float* __restrict__ mv, const float* __restrict__ mr,
    __half* kh, __half* vh, __half* rh)
{
    const int row = blockIdx.x, tid = threadIdx.x;
    const int t = row & (Tv - 1);
    const size_t i4 = (size_t)row * (Cv / 4) + tid;
    float4 xc = reinterpret_cast<const float4*>(x)[i4];
    float4 xp = make_float4(0.f, 0.f, 0.f, 0.f);
    if (t != 0) xp = reinterpret_cast<const float4*>(x)[i4 - (Cv / 4)];
    float sc, sp;
    norm2_reduce(xc.x*xc.x + xc.y*xc.y + xc.z*xc.z + xc.w*xc.w,
                 xp.x*xp.x + xp.y*xp.y + xp.z*xp.z + xp.w*xp.w, sc, sp);
    float4 wv = reinterpret_cast<const float4*>(w)[tid];
    float4 hv = make_float4(xc.x*sc*wv.x, xc.y*sc*wv.y, xc.z*sc*wv.z, xc.w*sc*wv.w);
    float4 sh = make_float4(xp.x*sp*wv.x, xp.y*sp*wv.y, xp.z*sp*wv.z, xp.w*sp*wv.w);
    const size_t e = i4 * 4;
    round4st(mixf4(reinterpret_cast<const float4*>(mk)[tid], hv, sh), kh, e);
    round4st(mixf4(reinterpret_cast<const float4*>(mv)[tid], hv, sh), vh, e);
    round4st(mixf4(reinterpret_cast<const float4*>(mr)[tid], hv, sh), rh, e);
}

__global__ void __launch_bounds__(256) fusedmix2_kernel(const float* __restrict__ x,
    const float* __restrict__ w,
    const float* __restrict__ mk, const float* __restrict__ mr,
    __half* kh, __half* rh)
{
    const int row = blockIdx.x, tid = threadIdx.x;
    const int t = row & (Tv - 1);
    const size_t i4 = (size_t)row * (Cv / 4) + tid;
    float4 xc = reinterpret_cast<const float4*>(x)[i4];
    float4 xp = make_float4(0.f, 0.f, 0.f, 0.f);
    if (t != 0) xp = reinterpret_cast<const float4*>(x)[i4 - (Cv / 4)];
    float sc, sp;
    norm2_reduce(xc.x*xc.x + xc.y*xc.y + xc.z*xc.z + xc.w*xc.w,
                 xp.x*xp.x + xp.y*xp.y + xp.z*xp.z + xp.w*xp.w, sc, sp);
    float4 wv = reinterpret_cast<const float4*>(w)[tid];
    float4 hv = make_float4(xc.x*sc*wv.x, xc.y*sc*wv.y, xc.z*sc*wv.z, xc.w*sc*wv.w);
    float4 sh = make_float4(xp.x*sp*wv.x, xp.y*sp*wv.y, xp.z*sp*wv.z, xp.w*sp*wv.w);
    const size_t e = i4 * 4;
    round4st(mixf4(reinterpret_cast<const float4*>(mk)[tid], hv, sh), kh, e);
    round4st(mixf4(reinterpret_cast<const float4*>(mr)[tid], hv, sh), rh, e);
}

// ===========================================================================
// Weight transpose: W[K,N] fp32 -> [N,K] fp16, 64x64 tiles, vectorized I/O
// ===========================================================================
__device__ __forceinline__ void wtrans_body(const float* W, __half* D, int K, int N) {
    __shared__ float t[64][69];
    const int tid = threadIdx.x;
    const int n0 = blockIdx.x * 64, k0 = blockIdx.y * 64;
    const int lk = tid >> 4, ln4 = (tid & 15) * 4;
#pragma unroll
    for (int r = 0; r < 4; r++) {
        const int krow = r * 16 + lk;
        const float4 vv = *reinterpret_cast<const float4*>(&W[(size_t)(k0 + krow) * N + n0 + ln4]);
        t[krow][ln4 + 0] = vv.x; t[krow][ln4 + 1] = vv.y;
        t[krow][ln4 + 2] = vv.z; t[krow][ln4 + 3] = vv.w;
    }
    __syncthreads();
#pragma unroll
    for (int u = 0; u < 2; u++) {
        const int unit = tid * 2 + u;
        const int n = unit >> 3, kc = (unit & 7) * 8;
        u32 p[4];
#pragma unroll
        for (int q = 0; q < 4; q++)
            p[q] = pack2h(t[kc + 2*q][n], t[kc + 2*q + 1][n]);
        *reinterpret_cast<uint4*>(&D[(size_t)(n0 + n) * K + k0 + kc]) =
            make_uint4(p[0], p[1], p[2], p[3]);
    }
}

__global__ void __launch_bounds__(256) wsplit5_kernel(
    const float* s0, const float* s1, const float* s2, const float* s3, const float* s4,
    __half* d0, __half* d1, __half* d2, __half* d3, __half* d4)
{
    const float* S; __half* D;
    switch (blockIdx.z) {
        case 0: S = s0; D = d0; break;
        case 1: S = s1; D = d1; break;
        case 2: S = s2; D = d2; break;
        case 3: S = s3; D = d3; break;
        default: S = s4; D = d4; break;
    }
    wtrans_body(S, D, Cv, Cv);
}

__global__ void __launch_bounds__(256) wsplit_kernel(const float* __restrict__ W,
    __half* __restrict__ D, int K, int N)
{
    wtrans_body(W, D, K, N);
}

// ===========================================================================
// WKV scan — exp-free, fp16 I/O (ek/v/r fp16; state math fp32)
// ===========================================================================
__global__ void __launch_bounds__(1024) wkv_pass1(const __half* __restrict__ ek,
    const __half* __restrict__ v, const float* __restrict__ td,
    float* __restrict__ sA, float* __restrict__ sB)
{
    const int c = threadIdx.x, chunk = blockIdx.x, b = blockIdx.y;
    const float ew = __expf(clip20(-__expf(td[c])));
    float a = 0.f, bb = 0.f;
    size_t base = ((size_t)(b * Tv) + (size_t)chunk * CLEN) * Cv + c;
    for (int t = 0; t < CLEN; t++) {
        const size_t ix = base + (size_t)t * Cv;
        const float e = __half2float(ek[ix]);
        a = ew * a + e * __half2float(v[ix]);  bb = ew * bb + e;
    }
    const int sidx = (b * NCHUNK + chunk) * Cv + c;
    sA[sidx] = a; sB[sidx] = bb;
}

__global__ void __launch_bounds__(1024) wkv_pass2(const float* __restrict__ td,
                                                  float* __restrict__ sA, float* __restrict__ sB)
{
    const int c = threadIdx.x, b = blockIdx.x;
    const float w = clip20(-__expf(td[c]));
    const float ewL = __expf(w * (float)CLEN);
    float Sa = 0.f, Sb = 0.f;
    for (int i = 0; i < NCHUNK; i++) {
        const int idx = (b * NCHUNK + i) * Cv + c;
        const float la = sA[idx], lb = sB[idx];
        sA[idx] = Sa; sB[idx] = Sb;
        Sa = ewL * Sa + la;  Sb = ewL * Sb + lb;
    }
}

__global__ void __launch_bounds__(1024) wkv_pass3(const __half* __restrict__ ek,
    const __half* __restrict__ v, const __half* __restrict__ r,
    const float* __restrict__ td, const float* __restrict__ tf,
    const float* __restrict__ sA, const float* __restrict__ sB,
    __half* __restrict__ oh)
{
    const int c = threadIdx.x, chunk = blockIdx.x, b = blockIdx.y;
    const float ew = __expf(clip20(-__expf(td[c])));
    const float eu = __expf(tf[c]);
    const int sidx = (b * NCHUNK + chunk) * Cv + c;
    float a = sA[sidx], bb = sB[sidx];
    size_t base = ((size_t)(b * Tv) + (size_t)chunk * CLEN) * Cv + c;
    for (int t = 0; t < CLEN; t++) {
        const size_t ix = base + (size_t)t * Cv;
        const float e = __half2float(ek[ix]);
        const float vt = __half2float(v[ix]);
        const float ekt = fminf(eu * e, EXP20F);   // = exp(clip(u+k)); clip inactive for |k|<~6
        const float o = __half2float(r[ix]) * __fdividef(a + ekt * vt, bb + ekt + 1e-8f);
        oh[ix] = __float2half_rn(o);
        a = ew * a + e * vt;  bb = ew * bb + e;
    }
}

// ===========================================================================
// HMMA fp16 GEMM core (R10 config verbatim — known-good 1715us):
// 128x128 tile, warp 32x64 (8 warps 4m x 2n), Kchunk=64, 3-stage, 2 CTAs/SM.
// D = A[M,K] @ B^T (B stored [N,K] K-major).
// ===========================================================================
#define STAGE_B 32768
#define GSMEM   (3 * STAGE_B)

__device__ __forceinline__ u32 swz(u32 o) { return o ^ ((o >> 3) & 0x70); }

template<int KDIM>
__device__ __forceinline__ void gemm_core(const __half* Abase, const __half* Bbase,
                                          int arow0, int brow0, char* smem,
                                          float acc[2][8][4])
{
    const u32 sbase = smem_to_u32(smem);
    const int tid = threadIdx.x, wid = tid >> 5, lane = tid & 31;

    const int lrow = tid >> 1;
    const int segb = (tid & 1) * 64;
    u32 soff[4];
#pragma unroll
    for (int j = 0; j < 4; j++) soff[j] = swz((u32)(lrow * 128 + segb + j * 16));
    const char* gA = (const char*)(Abase + (size_t)(arow0 + lrow) * KDIM) + segb;
    const char* gB = (const char*)(Bbase + (size_t)(brow0 + lrow) * KDIM) + segb;

    auto ld_chunk = [&](int stage, int c) {
        const u32 sb = sbase + stage * STAGE_B;
        const size_t go = (size_t)c * 128;
#pragma unroll
        for (int j = 0; j < 4; j++) cpasync16(sb + soff[j], gA + go + j * 16);
#pragma unroll
        for (int j = 0; j < 4; j++) cpasync16(sb + 16384 + soff[j], gB + go + j * 16);
        cpasync_commit();
    };

    const int wm = (wid & 3) * 32;
    const int wn = (wid >> 2) * 64;
    const int laneA_row = lane & 15;
    const int laneA_kb  = (lane >> 4) * 16;
    const int laneB_row = (lane & 7) | (((lane >> 4) & 1) << 3);
    const int laneB_kb  = ((lane >> 3) & 1) * 16;

#pragma unroll
    for (int i = 0; i < 2; i++)
#pragma unroll
        for (int j = 0; j < 8; j++)
#pragma unroll
            for (int q = 0; q < 4; q++) acc[i][j][q] = 0.f;

    constexpr int nch = KDIM >> 6;
    ld_chunk(0, 0); ld_chunk(1, 1); ld_chunk(2, 2);

    for (int c = 0; c < nch; ++c) {
        if      (c + 2 < nch) cpasync_wait<2>();
        else if (c + 1 < nch) cpasync_wait<1>();
        else                  cpasync_wait<0>();
        __syncthreads();

        const u32 sb = sbase + (c % 3) * STAGE_B;
#pragma unroll
        for (int ks = 0; ks < 4; ++ks) {
            const int kb = ks * 32;
            u32 ah[2][4], bh[4][4];
#pragma unroll
            for (int i = 0; i < 2; i++)
                ldsm4(ah[i], sb + swz((u32)((wm + 16 * i + laneA_row) * 128 + kb + laneA_kb)));
#pragma unroll
            for (int g = 0; g < 4; g++)
                ldsm4(bh[g], sb + 16384 + swz((u32)((wn + 16 * g + laneB_row) * 128 + kb + laneB_kb)));
#pragma unroll
            for (int i = 0; i < 2; i++)
#pragma unroll
                for (int j = 0; j < 8; j++)
                    mma16816(acc[i][j], ah[i], &bh[j >> 1][(j & 1) * 2]);
        }
        __syncthreads();
        if (c + 3 < nch) ld_chunk(c % 3, c + 3);
    }
}

#define EPI_SETUP() \
    const int wid = threadIdx.x >> 5, lane = threadIdx.x & 31; \
    const int wm = (wid & 3) * 32, wn = (wid >> 2) * 64; \
    const int gid = lane >> 2, tg = lane & 3;

// ---- fused k/v/r GEMM: grid (24, 128); x in [0,8)=k->exp16, [8,16)=v16, [16,24)=r->sigm16
__global__ void __launch_bounds__(256, 2) hgemm_kvr(
    const __half* __restrict__ A0, const __half* __restrict__ A1, const __half* __restrict__ A2,
    const __half* __restrict__ B0, const __half* __restrict__ B1, const __half* __restrict__ B2,
    __half* __restrict__ C0, __half* __restrict__ C1, __half* __restrict__ C2)
{
    extern __shared__ __align__(1024) char smem[];
    const int sel = blockIdx.x >> 3;
    const int bxe = blockIdx.x & 7;
    const __half* A = (sel == 0) ? A0 : ((sel == 1) ? A1 : A2);
    const __half* B = (sel == 0) ? B0 : ((sel == 1) ? B1 : B2);
    __half*      C = (sel == 0) ? C0 : ((sel == 1) ? C1 : C2);

    float acc[2][8][4];
    gemm_core<Cv>(A, B, blockIdx.y * 128, bxe * 128, smem, acc);

    EPI_SETUP();
    const int bm = blockIdx.y * 128, bn = bxe * 128;
#pragma unroll
    for (int i = 0; i < 2; i++) {
        const int r0 = bm + wm + 16 * i + gid;
#pragma unroll
        for (int j = 0; j < 8; j++) {
            const int cc = bn + wn + 8 * j + 2 * tg;
            const size_t idx0 = (size_t)r0 * Cv + cc;
            const size_t idx1 = idx0 + (size_t)8 * Cv;
            float v0 = acc[i][j][0], v1 = acc[i][j][1];
            float v2 = acc[i][j][2], v3 = acc[i][j][3];
            if (sel == 0) {
                v0 = __expf(clip20(v0)); v1 = __expf(clip20(v1));
                v2 = __expf(clip20(v2)); v3 = __expf(clip20(v3));
            } else if (sel == 2) {
                v0 = sigm(v0); v1 = sigm(v1); v2 = sigm(v2); v3 = sigm(v3);
            }
            *reinterpret_cast<u32*>(C + idx0) = pack2h(v0, v1);
            *reinterpret_cast<u32*>(C + idx1) = pack2h(v2, v3);
        }
    }
}

// ---- Wo GEMM: x1 = x + rw@Wo^T; grid (8, 128)
__global__ void __launch_bounds__(256, 2) hgemm_add(
    const __half* __restrict__ A, const __half* __restrict__ B,
    float* __restrict__ C, const float* __restrict__ E)
{
    extern __shared__ __align__(1024) char smem[];
    float acc[2][8][4];
    gemm_core<Cv>(A, B, blockIdx.y * 128, blockIdx.x * 128, smem, acc);

    EPI_SETUP();
    const int bm = blockIdx.y * 128, bn = blockIdx.x * 128;
#pragma unroll
    for (int i = 0; i < 2; i++) {
        const int r0 = bm + wm + 16 * i + gid;
#pragma unroll
        for (int j = 0; j < 8; j++) {
            const int cc = bn + wn + 8 * j + 2 * tg;
            const size_t idx0 = (size_t)r0 * Cv + cc;
            const size_t idx1 = idx0 + (size_t)8 * Cv;
            const float2 e0 = *reinterpret_cast<const float2*>(&E[idx0]);
            const float2 e1 = *reinterpret_cast<const float2*>(&E[idx1]);
            *reinterpret_cast<float2*>(&C[idx0]) = make_float2(acc[i][j][0] + e0.x, acc[i][j][1] + e0.y);
            *reinterpret_cast<float2*>(&C[idx1]) = make_float2(acc[i][j][2] + e1.x, acc[i][j][3] + e1.y);
        }
    }
}

// ---- fused k2/r2 GEMM: grid (40, 128); x<32: k2=relu^2 (fp16, N=Iv); x>=32: r2=sigm (fp32, N=Cv)
__global__ void __launch_bounds__(256, 2) hgemm_k2r2(
    const __half* __restrict__ A0, const __half* __restrict__ A1,
    const __half* __restrict__ B0, const __half* __restrict__ B1,
    __half* __restrict__ C0, float* __restrict__ C1)
{
    extern __shared__ __align__(1024) char smem[];
    const bool isr2 = (blockIdx.x >= 32);
    const int bxe = isr2 ? (blockIdx.x - 32) : blockIdx.x;
    const __half* A = isr2 ? A1 : A0;
    const __half* B = isr2 ? B1 : B0;

    float acc[2][8][4];
    gemm_core<Cv>(A, B, blockIdx.y * 128, bxe * 128, smem, acc);

    EPI_SETUP();
    const int bm = blockIdx.y * 128, bn = bxe * 128;
    const int N = isr2 ? Cv : Iv;
#pragma unroll
    for (int i = 0; i < 2; i++) {
        const int r0 = bm + wm + 16 * i + gid;
#pragma unroll
        for (int j = 0; j < 8; j++) {
            const int cc = bn + wn + 8 * j + 2 * tg;
            const size_t idx0 = (size_t)r0 * N + cc;
            const size_t idx1 = idx0 + (size_t)8 * N;
            float v0 = acc[i][j][0], v1 = acc[i][j][1];
            float v2 = acc[i][j][2], v3 = acc[i][j][3];
            if (!isr2) {
                v0 = fmaxf(v0, 0.f); v0 *= v0;  v1 = fmaxf(v1, 0.f); v1 *= v1;
                v2 = fmaxf(v2, 0.f); v2 *= v2;  v3 = fmaxf(v3, 0.f); v3 *= v3;
                *reinterpret_cast<u32*>(C0 + idx0) = pack2h(v0, v1);
                *reinterpret_cast<u32*>(C0 + idx1) = pack2h(v2, v3);
            } else {
                *reinterpret_cast<float2*>(&C1[idx0]) = make_float2(sigm(v0), sigm(v1));
                *reinterpret_cast<float2*>(&C1[idx1]) = make_float2(sigm(v2), sigm(v3));
            }
        }
    }
}

// ---- v2 GEMM (K=Iv): out = x1 + r2 * (k2@Wv2^T); grid (8, 128)
__global__ void __launch_bounds__(256, 2) hgemm_muladd(
    const __half* __restrict__ A, const __half* __restrict__ B,
    float* __restrict__ C, const float* __restrict__ E1, const float* __restrict__ E2)
{
    extern __shared__ __align__(1024) char smem[];
    float acc[2][8][4];
    gemm_core<Iv>(A, B, blockIdx.y * 128, blockIdx.x * 128, smem, acc);

    EPI_SETUP();
    const int bm = blockIdx.y * 128, bn = blockIdx.x * 128;
#pragma unroll
    for (int i = 0; i < 2; i++) {
        const int r0 = bm + wm + 16 * i + gid;
#pragma unroll
        for (int j = 0; j < 8; j++) {
            const int cc = bn + wn + 8 * j + 2 * tg;
            const size_t idx0 = (size_t)r0 * Cv + cc;
            const size_t idx1 = idx0 + (size_t)8 * Cv;
            const float2 a0 = *reinterpret_cast<const float2*>(&E1[idx0]);
            const float2 a1 = *reinterpret_cast<const float2*>(&E1[idx1]);
            const float2 m0 = *reinterpret_cast<const float2*>(&E2[idx0]);
            const float2 m1 = *reinterpret_cast<const float2*>(&E2[idx1]);
            *reinterpret_cast<float2*>(&C[idx0]) =
                make_float2(a0.x + m0.x * acc[i][j][0], a0.y + m0.y * acc[i][j][1]);
            *reinterpret_cast<float2*>(&C[idx1]) =
                make_float2(a1.x + m1.x * acc[i][j][2], a1.y + m1.y * acc[i][j][3]);
        }
    }
}

// ===========================================================================
// Launch
// ===========================================================================
extern "C" void kernel_launch(void* const* d_in, const int* in_sizes, int n_in,
                              void* d_out, int out_size)
{
    const float* x     = (const float*)d_in[0];
    const float* ln1_w = (const float*)d_in[1];
    const float* ln2_w = (const float*)d_in[2];
    const float* td    = (const float*)d_in[3];
    const float* tf    = (const float*)d_in[4];
    const float* mk    = (const float*)d_in[5];
    const float* mv    = (const float*)d_in[6];
    const float* mr    = (const float*)d_in[7];
    const float* Wk    = (const float*)d_in[8];
    const float* Wv    = (const float*)d_in[9];
    const float* Wr    = (const float*)d_in[10];
    const float* Wo    = (const float*)d_in[11];
    const float* mk2   = (const float*)d_in[12];
    const float* mr2   = (const float*)d_in[13];
    const float* Wk2   = (const float*)d_in[14];
    const float* Wv2   = (const float*)d_in[15];
    const float* Wr2   = (const float*)d_in[16];
    float* out = (float*)d_out;

#define SYM(p, s) void* p##_; cudaGetSymbolAddress(&p##_, s); auto* p = (decltype(&s[0]))p##_
    SYM(ek,  g_ek); SYM(v,   g_v);  SYM(r,   g_r);
    SYM(x1,  g_x1); SYM(r2,  g_r2); SYM(sA,  g_sA); SYM(sB,  g_sB);
    SYM(xkh, a_xk_h); SYM(xvh, a_xv_h); SYM(xrh, a_xr_h);
    SYM(rwh, a_rw_h); SYM(k2h, a_k2_h);
    SYM(wkh, w_k_h);  SYM(wvh, w_v_h);  SYM(wrh, w_r_h);  SYM(woh, w_o_h);
    SYM(wr2h, w_r2_h); SYM(wk2h, w_k2_h); SYM(wv2h, w_v2_h);
#undef SYM

    cudaFuncSetAttribute(hgemm_kvr,    cudaFuncAttributeMaxDynamicSharedMemorySize, GSMEM);
    cudaFuncSetAttribute(hgemm_add,    cudaFuncAttributeMaxDynamicSharedMemorySize, GSMEM);
    cudaFuncSetAttribute(hgemm_k2r2,   cudaFuncAttributeMaxDynamicSharedMemorySize, GSMEM);
    cudaFuncSetAttribute(hgemm_muladd, cudaFuncAttributeMaxDynamicSharedMemorySize, GSMEM);

    // weight transposes (64x64 tiles, vectorized)
    wsplit5_kernel<<<dim3(Cv/64, Cv/64, 5), 256>>>(Wk, Wv, Wr, Wo, Wr2,
                                                   wkh, wvh, wrh, woh, wr2h);
    wsplit_kernel<<<dim3(Iv/64, Cv/64), 256>>>(Wk2, wk2h, Cv, Iv);  // [C,I] -> [I,C]
    wsplit_kernel<<<dim3(Cv/64, Iv/64), 256>>>(Wv2, wv2h, Iv, Cv);  // [I,C] -> [C,I]

    // --- time mixing ---
    fusedmix3_kernel<<<Mv, 256>>>(x, ln1_w, mk, mv, mr, xkh, xvh, xrh);
    hgemm_kvr<<<dim3(24, 128), 256, GSMEM>>>(xkh, xvh, xrh, wkh, wvh, wrh, ek, v, r);
    wkv_pass1<<<dim3(NCHUNK, Bv), Cv>>>(ek, v, td, sA, sB);
    wkv_pass2<<<Bv, Cv>>>(td, sA, sB);
    wkv_pass3<<<dim3(NCHUNK, Bv), Cv>>>(ek, v, r, td, tf, sA, sB, rwh);
    hgemm_add<<<dim3(8, 128), 256, GSMEM>>>(rwh, woh, x1, x);

    // --- channel mixing ---
    fusedmix2_kernel<<<Mv, 256>>>(x1, ln2_w, mk2, mr2, xkh, xrh);
    hgemm_k2r2<<<dim3(40, 128), 256, GSMEM>>>(xkh, xrh, wk2h, wr2h, k2h, r2);
    hgemm_muladd<<<dim3(8, 128), 256, GSMEM>>>(k2h, wv2h, out, x1, r2);
}

// round 15
// speedup vs baseline: 1.3543x; 1.0031x over previous
#include <cuda_runtime.h>
#include <cuda_fp16.h>
#include <cstdint>

#define Bv 4
#define Tv 4096
#define Cv 1024
#define Iv 4096
#define Mv (Bv * Tv)          // 16384 tokens
#define NCHUNK 64
#define CLEN (Tv / NCHUNK)    // 64

typedef unsigned int u32;

// ===========================================================================
// PTX helpers (sm_80-era only — bare compute_103 target rejects tcgen05)
// ===========================================================================
__device__ __forceinline__ u32 smem_to_u32(const void* p) {
    u32 a;
    asm("{ .reg .u64 t; cvta.to.shared.u64 t, %1; cvt.u32.u64 %0, t; }" : "=r"(a) : "l"(p));
    return a;
}
__device__ __forceinline__ void ldsm4(u32* r, u32 addr) {
    asm volatile("ldmatrix.sync.aligned.m8n8.x4.shared.b16 {%0,%1,%2,%3}, [%4];"
                 : "=r"(r[0]), "=r"(r[1]), "=r"(r[2]), "=r"(r[3]) : "r"(addr));
}
__device__ __forceinline__ void mma16816(float* c, const u32* a, const u32* b) {
    asm volatile("mma.sync.aligned.m16n8k16.row.col.f32.f16.f16.f32 "
                 "{%0,%1,%2,%3}, {%4,%5,%6,%7}, {%8,%9}, {%0,%1,%2,%3};"
                 : "+f"(c[0]), "+f"(c[1]), "+f"(c[2]), "+f"(c[3])
                 : "r"(a[0]), "r"(a[1]), "r"(a[2]), "r"(a[3]), "r"(b[0]), "r"(b[1]));
}
__device__ __forceinline__ void cpasync16(u32 s, const void* g) {
    asm volatile("cp.async.cg.shared.global [%0], [%1], 16;" :: "r"(s), "l"(g));
}
__device__ __forceinline__ void cpasync_commit() { asm volatile("cp.async.commit_group;" ::: "memory"); }
template<int N> __device__ __forceinline__ void cpasync_wait() {
    asm volatile("cp.async.wait_group %0;" :: "n"(N) : "memory");
}

// ===========================================================================
// Scratch (__device__ globals; allocation-free)
// ===========================================================================
__device__ __half g_ek [(size_t)Mv * Cv];     // exp(clip(k)) fp16 — k-GEMM epilogue
__device__ __half g_v  [(size_t)Mv * Cv];     // fp16
__device__ __half g_r  [(size_t)Mv * Cv];     // fp16 sigmoid
__device__ float  g_x1 [(size_t)Mv * Cv];
__device__ float  g_r2 [(size_t)Mv * Cv];
__device__ float  g_sA [Bv * NCHUNK * Cv];
__device__ float  g_sB [Bv * NCHUNK * Cv];

__device__ __half a_xk_h[(size_t)Mv * Cv];
__device__ __half a_xv_h[(size_t)Mv * Cv];
__device__ __half a_xr_h[(size_t)Mv * Cv];
__device__ __half a_rw_h[(size_t)Mv * Cv];
__device__ __half a_k2_h[(size_t)Mv * Iv];

// weights transposed to [N,K] K-major fp16
__device__ __half w_k_h [Cv * Cv];
__device__ __half w_v_h [Cv * Cv];
__device__ __half w_r_h [Cv * Cv];
__device__ __half w_o_h [Cv * Cv];
__device__ __half w_r2_h[Cv * Cv];
__device__ __half w_k2_h[(size_t)Iv * Cv];
__device__ __half w_v2_h[(size_t)Cv * Iv];

// ===========================================================================
// Numeric helpers
// ===========================================================================
#define EXP20F 4.851652e8f
__device__ __forceinline__ float clip20(float x) { return fminf(fmaxf(x, -20.f), 20.f); }

// MUFU-free exp: 2^(x*log2e), rint + degree-6 Taylor on [-0.5,0.5] + exponent
// scale. Input must be in [-30, 30]. Rel err ~2e-7.
__device__ __forceinline__ float fast_exp(float x) {
    const float y = x * 1.4426950408889634f;
    const float j = rintf(y);
    const float f = y - j;
    float p = 1.5403530e-4f;
    p = fmaf(p, f, 1.3333558e-3f);
    p = fmaf(p, f, 9.6181291e-3f);
    p = fmaf(p, f, 5.5504109e-2f);
    p = fmaf(p, f, 2.4022651e-1f);
    p = fmaf(p, f, 6.9314718e-1f);
    p = fmaf(p, f, 1.0f);
    return p * __int_as_float(((int)j + 127) << 23);
}
// MUFU-free reciprocal: bit-trick seed + 3 Newton steps. d must be positive
// normal. Rel err ~1e-8.
__device__ __forceinline__ float fast_rcp(float d) {
    float r = __int_as_float(0x7EF311C3u - __float_as_uint(d));
    r = r * fmaf(-d, r, 2.0f);
    r = r * fmaf(-d, r, 2.0f);
    r = r * fmaf(-d, r, 2.0f);
    return r;
}
__device__ __forceinline__ float sigm(float x) {
    const float xc = fminf(fmaxf(x, -30.f), 30.f);
    return fast_rcp(1.0f + fast_exp(-xc));
}

__device__ __forceinline__ u32 pack2h(float a, float b) {
    __half ha = __float2half_rn(a), hb = __float2half_rn(b);
    return (u32)(*(uint16_t*)&ha) | ((u32)(*(uint16_t*)&hb) << 16);
}
__device__ __forceinline__ void round4st(float4 v, __half* Hi, size_t e) {
    *reinterpret_cast<uint2*>(Hi + e) = make_uint2(pack2h(v.x, v.y), pack2h(v.z, v.w));
}
__device__ __forceinline__ float4 mixf4(float4 m, float4 h, float4 s) {
    float4 o;
    o.x = m.x * h.x + (1.f - m.x) * s.x;
    o.y = m.y * h.y + (1.f - m.y) * s.y;
    o.z = m.z * h.z + (1.f - m.z) * s.z;
    o.w = m.w * h.w + (1.f - m.w) * s.w;
    return o;
}

// ===========================================================================
// Fused RMSNorm + token-shift mix
// ===========================================================================
__device__ __forceinline__ void norm2_reduce(float sc, float sp, float& oc, float& op) {
#pragma unroll
    for (int o = 16; o > 0; o >>= 1) {
        sc += __shfl_xor_sync(0xffffffffu, sc, o);
        sp += __shfl_xor_sync(0xffffffffu, sp, o);
    }
    __shared__ float rc[8], rp[8];
    const int tid = threadIdx.x;
    if ((tid & 31) == 0) { rc[tid >> 5] = sc; rp[tid >> 5] = sp; }
    __syncthreads();
    float tc = 0.f, tp = 0.f;
#pragma unroll
    for (int i = 0; i < 8; i++) { tc += rc[i]; tp += rp[i]; }
    oc = rsqrtf(tc * (1.0f / (float)Cv) + 1e-6f);
    op = rsqrtf(tp * (1.0f / (float)Cv) + 1e-6f);
}

__global__ void __launch_bounds__(256) fusedmix3_kernel(const float* __restrict__ x,
    const float* __restrict__ w,
    const float* __restrict__ mk, const float* __restrict__ mv, const float* __restrict__ mr,
    __half* kh, __half* vh, __half* rh)
{
    const int row = blockIdx.x, tid = threadIdx.x;
    const int t = row & (Tv - 1);
    const size_t i4 = (size_t)row * (Cv / 4) + tid;
    float4 xc = reinterpret_cast<const float4*>(x)[i4];
    float4 xp = make_float4(0.f, 0.f, 0.f, 0.f);
    if (t != 0) xp = reinterpret_cast<const float4*>(x)[i4 - (Cv / 4)];
    float sc, sp;
    norm2_reduce(xc.x*xc.x + xc.y*xc.y + xc.z*xc.z + xc.w*xc.w,
                 xp.x*xp.x + xp.y*xp.y + xp.z*xp.z + xp.w*xp.w, sc, sp);
    float4 wv = reinterpret_cast<const float4*>(w)[tid];
    float4 hv = make_float4(xc.x*sc*wv.x, xc.y*sc*wv.y, xc.z*sc*wv.z, xc.w*sc*wv.w);
    float4 sh = make_float4(xp.x*sp*wv.x, xp.y*sp*wv.y, xp.z*sp*wv.z, xp.w*sp*wv.w);
    const size_t e = i4 * 4;
    round4st(mixf4(reinterpret_cast<const float4*>(mk)[tid], hv, sh), kh, e);
    round4st(mixf4(reinterpret_cast<const float4*>(mv)[tid], hv, sh), vh, e);
    round4st(mixf4(reinterpret_cast<const float4*>(mr)[tid], hv, sh), rh, e);
}

__global__ void __launch_bounds__(256) fusedmix2_kernel(const float* __restrict__ x,
    const float* __restrict__ w,
    const float* __restrict__ mk, const float* __restrict__ mr,
    __half* kh, __half* rh)
{
    const int row = blockIdx.x, tid = threadIdx.x;
    const int t = row & (Tv - 1);
    const size_t i4 = (size_t)row * (Cv / 4) + tid;
    float4 xc = reinterpret_cast<const float4*>(x)[i4];
    float4 xp = make_float4(0.f, 0.f, 0.f, 0.f);
    if (t != 0) xp = reinterpret_cast<const float4*>(x)[i4 - (Cv / 4)];
    float sc, sp;
    norm2_reduce(xc.x*xc.x + xc.y*xc.y + xc.z*xc.z + xc.w*xc.w,
                 xp.x*xp.x + xp.y*xp.y + xp.z*xp.z + xp.w*xp.w, sc, sp);
    float4 wv = reinterpret_cast<const float4*>(w)[tid];
    float4 hv = make_float4(xc.x*sc*wv.x, xc.y*sc*wv.y, xc.z*sc*wv.z, xc.w*sc*wv.w);
    float4 sh = make_float4(xp.x*sp*wv.x, xp.y*sp*wv.y, xp.z*sp*wv.z, xp.w*sp*wv.w);
    const size_t e = i4 * 4;
    round4st(mixf4(reinterpret_cast<const float4*>(mk)[tid], hv, sh), kh, e);
    round4st(mixf4(reinterpret_cast<const float4*>(mr)[tid], hv, sh), rh, e);
}

// ===========================================================================
// Weight transpose: W[K,N] fp32 -> [N,K] fp16, 64x64 tiles, vectorized I/O
// ===========================================================================
__device__ __forceinline__ void wtrans_body(const float* W, __half* D, int K, int N) {
    __shared__ float t[64][69];
    const int tid = threadIdx.x;
    const int n0 = blockIdx.x * 64, k0 = blockIdx.y * 64;
    const int lk = tid >> 4, ln4 = (tid & 15) * 4;
#pragma unroll
    for (int r = 0; r < 4; r++) {
        const int krow = r * 16 + lk;
        const float4 vv = *reinterpret_cast<const float4*>(&W[(size_t)(k0 + krow) * N + n0 + ln4]);
        t[krow][ln4 + 0] = vv.x; t[krow][ln4 + 1] = vv.y;
        t[krow][ln4 + 2] = vv.z; t[krow][ln4 + 3] = vv.w;
    }
    __syncthreads();
#pragma unroll
    for (int u = 0; u < 2; u++) {
        const int unit = tid * 2 + u;
        const int n = unit >> 3, kc = (unit & 7) * 8;
        u32 p[4];
#pragma unroll
        for (int q = 0; q < 4; q++)
            p[q] = pack2h(t[kc + 2*q][n], t[kc + 2*q + 1][n]);
        *reinterpret_cast<uint4*>(&D[(size_t)(n0 + n) * K + k0 + kc]) =
            make_uint4(p[0], p[1], p[2], p[3]);
    }
}

__global__ void __launch_bounds__(256) wsplit5_kernel(
    const float* s0, const float* s1, const float* s2, const float* s3, const float* s4,
    __half* d0, __half* d1, __half* d2, __half* d3, __half* d4)
{
    const float* S; __half* D;
    switch (blockIdx.z) {
        case 0: S = s0; D = d0; break;
        case 1: S = s1; D = d1; break;
        case 2: S = s2; D = d2; break;
        case 3: S = s3; D = d3; break;
        default: S = s4; D = d4; break;
    }
    wtrans_body(S, D, Cv, Cv);
}

__global__ void __launch_bounds__(256) wsplit_kernel(const float* __restrict__ W,
    __half* __restrict__ D, int K, int N)
{
    wtrans_body(W, D, K, N);
}

// ===========================================================================
// WKV scan — exp-free, fp16 I/O, MUFU-free division in pass3
// ===========================================================================
__global__ void __launch_bounds__(1024) wkv_pass1(const __half* __restrict__ ek,
    const __half* __restrict__ v, const float* __restrict__ td,
    float* __restrict__ sA, float* __restrict__ sB)
{
    const int c = threadIdx.x, chunk = blockIdx.x, b = blockIdx.y;
    const float ew = __expf(clip20(-__expf(td[c])));
    float a = 0.f, bb = 0.f;
    size_t base = ((size_t)(b * Tv) + (size_t)chunk * CLEN) * Cv + c;
    for (int t = 0; t < CLEN; t++) {
        const size_t ix = base + (size_t)t * Cv;
        const float e = __half2float(ek[ix]);
        a = ew * a + e * __half2float(v[ix]);  bb = ew * bb + e;
    }
    const int sidx = (b * NCHUNK + chunk) * Cv + c;
    sA[sidx] = a; sB[sidx] = bb;
}

__global__ void __launch_bounds__(1024) wkv_pass2(const float* __restrict__ td,
                                                  float* __restrict__ sA, float* __restrict__ sB)
{
    const int c = threadIdx.x, b = blockIdx.x;
    const float w = clip20(-__expf(td[c]));
    const float ewL = __expf(w * (float)CLEN);
    float Sa = 0.f, Sb = 0.f;
    for (int i = 0; i < NCHUNK; i++) {
        const int idx = (b * NCHUNK + i) * Cv + c;
        const float la = sA[idx], lb = sB[idx];
        sA[idx] = Sa; sB[idx] = Sb;
        Sa = ewL * Sa + la;  Sb = ewL * Sb + lb;
    }
}

__global__ void __launch_bounds__(1024) wkv_pass3(const __half* __restrict__ ek,
    const __half* __restrict__ v, const __half* __restrict__ r,
    const float* __restrict__ td, const float* __restrict__ tf,
    const float* __restrict__ sA, const float* __restrict__ sB,
    __half* __restrict__ oh)
{
    const int c = threadIdx.x, chunk = blockIdx.x, b = blockIdx.y;
    const float ew = __expf(clip20(-__expf(td[c])));
    const float eu = __expf(tf[c]);
    const int sidx = (b * NCHUNK + chunk) * Cv + c;
    float a = sA[sidx], bb = sB[sidx];
    size_t base = ((size_t)(b * Tv) + (size_t)chunk * CLEN) * Cv + c;
    for (int t = 0; t < CLEN; t++) {
        const size_t ix = base + (size_t)t * Cv;
        const float e = __half2float(ek[ix]);
        const float vt = __half2float(v[ix]);
        const float ekt = fminf(eu * e, EXP20F);   // = exp(clip(u+k)); clip inactive for |k|<~6
        const float o = __half2float(r[ix]) *
                        ((a + ekt * vt) * fast_rcp(bb + ekt + 1e-8f));
        oh[ix] = __float2half_rn(o);
        a = ew * a + e * vt;  bb = ew * bb + e;
    }
}

// ===========================================================================
// HMMA fp16 GEMM core (R10 config verbatim):
// 128x128 tile, warp 32x64 (8 warps 4m x 2n), Kchunk=64, 3-stage, 2 CTAs/SM.
// D = A[M,K] @ B^T (B stored [N,K] K-major).
// ===========================================================================
#define STAGE_B 32768
#define GSMEM   (3 * STAGE_B)

__device__ __forceinline__ u32 swz(u32 o) { return o ^ ((o >> 3) & 0x70); }

template<int KDIM>
__device__ __forceinline__ void gemm_core(const __half* Abase, const __half* Bbase,
                                          int arow0, int brow0, char* smem,
                                          float acc[2][8][4])
{
    const u32 sbase = smem_to_u32(smem);
    const int tid = threadIdx.x, wid = tid >> 5, lane = tid & 31;

    const int lrow = tid >> 1;
    const int segb = (tid & 1) * 64;
    u32 soff[4];
#pragma unroll
    for (int j = 0; j < 4; j++) soff[j] = swz((u32)(lrow * 128 + segb + j * 16));
    const char* gA = (const char*)(Abase + (size_t)(arow0 + lrow) * KDIM) + segb;
    const char* gB = (const char*)(Bbase + (size_t)(brow0 + lrow) * KDIM) + segb;

    auto ld_chunk = [&](int stage, int c) {
        const u32 sb = sbase + stage * STAGE_B;
        const size_t go = (size_t)c * 128;
#pragma unroll
        for (int j = 0; j < 4; j++) cpasync16(sb + soff[j], gA + go + j * 16);
#pragma unroll
        for (int j = 0; j < 4; j++) cpasync16(sb + 16384 + soff[j], gB + go + j * 16);
        cpasync_commit();
    };

    const int wm = (wid & 3) * 32;
    const int wn = (wid >> 2) * 64;
    const int laneA_row = lane & 15;
    const int laneA_kb  = (lane >> 4) * 16;
    const int laneB_row = (lane & 7) | (((lane >> 4) & 1) << 3);
    const int laneB_kb  = ((lane >> 3) & 1) * 16;

#pragma unroll
    for (int i = 0; i < 2; i++)
#pragma unroll
        for (int j = 0; j < 8; j++)
#pragma unroll
            for (int q = 0; q < 4; q++) acc[i][j][q] = 0.f;

    constexpr int nch = KDIM >> 6;
    ld_chunk(0, 0); ld_chunk(1, 1); ld_chunk(2, 2);

    for (int c = 0; c < nch; ++c) {
        if      (c + 2 < nch) cpasync_wait<2>();
        else if (c + 1 < nch) cpasync_wait<1>();
        else                  cpasync_wait<0>();
        __syncthreads();

        const u32 sb = sbase + (c % 3) * STAGE_B;
#pragma unroll
        for (int ks = 0; ks < 4; ++ks) {
            const int kb = ks * 32;
            u32 ah[2][4], bh[4][4];
#pragma unroll
            for (int i = 0; i < 2; i++)
                ldsm4(ah[i], sb + swz((u32)((wm + 16 * i + laneA_row) * 128 + kb + laneA_kb)));
#pragma unroll
            for (int g = 0; g < 4; g++)
                ldsm4(bh[g], sb + 16384 + swz((u32)((wn + 16 * g + laneB_row) * 128 + kb + laneB_kb)));
#pragma unroll
            for (int i = 0; i < 2; i++)
#pragma unroll
                for (int j = 0; j < 8; j++)
                    mma16816(acc[i][j], ah[i], &bh[j >> 1][(j & 1) * 2]);
        }
        __syncthreads();
        if (c + 3 < nch) ld_chunk(c % 3, c + 3);
    }
}

#define EPI_SETUP() \
    const int wid = threadIdx.x >> 5, lane = threadIdx.x & 31; \
    const int wm = (wid & 3) * 32, wn = (wid >> 2) * 64; \
    const int gid = lane >> 2, tg = lane & 3;

// ---- fused k/v/r GEMM: grid (24, 128); x in [0,8)=k->exp16, [8,16)=v16, [16,24)=r->sigm16
__global__ void __launch_bounds__(256, 2) hgemm_kvr(
    const __half* __restrict__ A0, const __half* __restrict__ A1, const __half* __restrict__ A2,
    const __half* __restrict__ B0, const __half* __restrict__ B1, const __half* __restrict__ B2,
    __half* __restrict__ C0, __half* __restrict__ C1, __half* __restrict__ C2)
{
    extern __shared__ __align__(1024) char smem[];
    const int sel = blockIdx.x >> 3;
    const int bxe = blockIdx.x & 7;
    const __half* A = (sel == 0) ? A0 : ((sel == 1) ? A1 : A2);
    const __half* B = (sel == 0) ? B0 : ((sel == 1) ? B1 : B2);
    __half*      C = (sel == 0) ? C0 : ((sel == 1) ? C1 : C2);

    float acc[2][8][4];
    gemm_core<Cv>(A, B, blockIdx.y * 128, bxe * 128, smem, acc);

    EPI_SETUP();
    const int bm = blockIdx.y * 128, bn = bxe * 128;
#pragma unroll
    for (int i = 0; i < 2; i++) {
        const int r0 = bm + wm + 16 * i + gid;
#pragma unroll
        for (int j = 0; j < 8; j++) {
            const int cc = bn + wn + 8 * j + 2 * tg;
            const size_t idx0 = (size_t)r0 * Cv + cc;
            const size_t idx1 = idx0 + (size_t)8 * Cv;
            float v0 = acc[i][j][0], v1 = acc[i][j][1];
            float v2 = acc[i][j][2], v3 = acc[i][j][3];
            if (sel == 0) {
                v0 = fast_exp(clip20(v0)); v1 = fast_exp(clip20(v1));
                v2 = fast_exp(clip20(v2)); v3 = fast_exp(clip20(v3));
            } else if (sel == 2) {
                v0 = sigm(v0); v1 = sigm(v1); v2 = sigm(v2); v3 = sigm(v3);
            }
            *reinterpret_cast<u32*>(C + idx0) = pack2h(v0, v1);
            *reinterpret_cast<u32*>(C + idx1) = pack2h(v2, v3);
        }
    }
}

// ---- Wo GEMM: x1 = x + rw@Wo^T; grid (8, 128)
__global__ void __launch_bounds__(256, 2) hgemm_add(
    const __half* __restrict__ A, const __half* __restrict__ B,
    float* __restrict__ C, const float* __restrict__ E)
{
    extern __shared__ __align__(1024) char smem[];
    float acc[2][8][4];
    gemm_core<Cv>(A, B, blockIdx.y * 128, blockIdx.x * 128, smem, acc);

    EPI_SETUP();
    const int bm = blockIdx.y * 128, bn = blockIdx.x * 128;
#pragma unroll
    for (int i = 0; i < 2; i++) {
        const int r0 = bm + wm + 16 * i + gid;
#pragma unroll
        for (int j = 0; j < 8; j++) {
            const int cc = bn + wn + 8 * j + 2 * tg;
            const size_t idx0 = (size_t)r0 * Cv + cc;
            const size_t idx1 = idx0 + (size_t)8 * Cv;
            const float2 e0 = *reinterpret_cast<const float2*>(&E[idx0]);
            const float2 e1 = *reinterpret_cast<const float2*>(&E[idx1]);
            *reinterpret_cast<float2*>(&C[idx0]) = make_float2(acc[i][j][0] + e0.x, acc[i][j][1] + e0.y);
            *reinterpret_cast<float2*>(&C[idx1]) = make_float2(acc[i][j][2] + e1.x, acc[i][j][3] + e1.y);
        }
    }
}

// ---- fused k2/r2 GEMM: grid (40, 128); x<32: k2=relu^2 (fp16, N=Iv); x>=32: r2=sigm (fp32, N=Cv)
__global__ void __launch_bounds__(256, 2) hgemm_k2r2(
    const __half* __restrict__ A0, const __half* __restrict__ A1,
    const __half* __restrict__ B0, const __half* __restrict__ B1,
    __half* __restrict__ C0, float* __restrict__ C1)
{
    extern __shared__ __align__(1024) char smem[];
    const bool isr2 = (blockIdx.x >= 32);
    const int bxe = isr2 ? (blockIdx.x - 32) : blockIdx.x;
    const __half* A = isr2 ? A1 : A0;
    const __half* B = isr2 ? B1 : B0;

    float acc[2][8][4];
    gemm_core<Cv>(A, B, blockIdx.y * 128, bxe * 128, smem, acc);

    EPI_SETUP();
    const int bm = blockIdx.y * 128, bn = bxe * 128;
    const int N = isr2 ? Cv : Iv;
#pragma unroll
    for (int i = 0; i < 2; i++) {
        const int r0 = bm + wm + 16 * i + gid;
#pragma unroll
        for (int j = 0; j < 8; j++) {
            const int cc = bn + wn + 8 * j + 2 * tg;
            const size_t idx0 = (size_t)r0 * N + cc;
            const size_t idx1 = idx0 + (size_t)8 * N;
            float v0 = acc[i][j][0], v1 = acc[i][j][1];
            float v2 = acc[i][j][2], v3 = acc[i][j][3];
            if (!isr2) {
                v0 = fmaxf(v0, 0.f); v0 *= v0;  v1 = fmaxf(v1, 0.f); v1 *= v1;
                v2 = fmaxf(v2, 0.f); v2 *= v2;  v3 = fmaxf(v3, 0.f); v3 *= v3;
                *reinterpret_cast<u32*>(C0 + idx0) = pack2h(v0, v1);
                *reinterpret_cast<u32*>(C0 + idx1) = pack2h(v2, v3);
            } else {
                *reinterpret_cast<float2*>(&C1[idx0]) = make_float2(sigm(v0), sigm(v1));
                *reinterpret_cast<float2*>(&C1[idx1]) = make_float2(sigm(v2), sigm(v3));
            }
        }
    }
}

// ---- v2 GEMM (K=Iv): out = x1 + r2 * (k2@Wv2^T); grid (8, 128)
__global__ void __launch_bounds__(256, 2) hgemm_muladd(
    const __half* __restrict__ A, const __half* __restrict__ B,
    float* __restrict__ C, const float* __restrict__ E1, const float* __restrict__ E2)
{
    extern __shared__ __align__(1024) char smem[];
    float acc[2][8][4];
    gemm_core<Iv>(A, B, blockIdx.y * 128, blockIdx.x * 128, smem, acc);

    EPI_SETUP();
    const int bm = blockIdx.y * 128, bn = blockIdx.x * 128;
#pragma unroll
    for (int i = 0; i < 2; i++) {
        const int r0 = bm + wm + 16 * i + gid;
#pragma unroll
        for (int j = 0; j < 8; j++) {
            const int cc = bn + wn + 8 * j + 2 * tg;
            const size_t idx0 = (size_t)r0 * Cv + cc;
            const size_t idx1 = idx0 + (size_t)8 * Cv;
            const float2 a0 = *reinterpret_cast<const float2*>(&E1[idx0]);
            const float2 a1 = *reinterpret_cast<const float2*>(&E1[idx1]);
            const float2 m0 = *reinterpret_cast<const float2*>(&E2[idx0]);
            const float2 m1 = *reinterpret_cast<const float2*>(&E2[idx1]);
            *reinterpret_cast<float2*>(&C[idx0]) =
                make_float2(a0.x + m0.x * acc[i][j][0], a0.y + m0.y * acc[i][j][1]);
            *reinterpret_cast<float2*>(&C[idx1]) =
                make_float2(a1.x + m1.x * acc[i][j][2], a1.y + m1.y * acc[i][j][3]);
        }
    }
}

// ===========================================================================
// Launch
// ===========================================================================
extern "C" void kernel_launch(void* const* d_in, const int* in_sizes, int n_in,
                              void* d_out, int out_size)
{
    const float* x     = (const float*)d_in[0];
    const float* ln1_w = (const float*)d_in[1];
    const float* ln2_w = (const float*)d_in[2];
    const float* td    = (const float*)d_in[3];
    const float* tf    = (const float*)d_in[4];
    const float* mk    = (const float*)d_in[5];
    const float* mv    = (const float*)d_in[6];
    const float* mr    = (const float*)d_in[7];
    const float* Wk    = (const float*)d_in[8];
    const float* Wv    = (const float*)d_in[9];
    const float* Wr    = (const float*)d_in[10];
    const float* Wo    = (const float*)d_in[11];
    const float* mk2   = (const float*)d_in[12];
    const float* mr2   = (const float*)d_in[13];
    const float* Wk2   = (const float*)d_in[14];
    const float* Wv2   = (const float*)d_in[15];
    const float* Wr2   = (const float*)d_in[16];
    float* out = (float*)d_out;

#define SYM(p, s) void* p##_; cudaGetSymbolAddress(&p##_, s); auto* p = (decltype(&s[0]))p##_
    SYM(ek,  g_ek); SYM(v,   g_v);  SYM(r,   g_r);
    SYM(x1,  g_x1); SYM(r2,  g_r2); SYM(sA,  g_sA); SYM(sB,  g_sB);
    SYM(xkh, a_xk_h); SYM(xvh, a_xv_h); SYM(xrh, a_xr_h);
    SYM(rwh, a_rw_h); SYM(k2h, a_k2_h);
    SYM(wkh, w_k_h);  SYM(wvh, w_v_h);  SYM(wrh, w_r_h);  SYM(woh, w_o_h);
    SYM(wr2h, w_r2_h); SYM(wk2h, w_k2_h); SYM(wv2h, w_v2_h);
#undef SYM

    cudaFuncSetAttribute(hgemm_kvr,    cudaFuncAttributeMaxDynamicSharedMemorySize, GSMEM);
    cudaFuncSetAttribute(hgemm_add,    cudaFuncAttributeMaxDynamicSharedMemorySize, GSMEM);
    cudaFuncSetAttribute(hgemm_k2r2,   cudaFuncAttributeMaxDynamicSharedMemorySize, GSMEM);
    cudaFuncSetAttribute(hgemm_muladd, cudaFuncAttributeMaxDynamicSharedMemorySize, GSMEM);

    // weight transposes (64x64 tiles, vectorized)
    wsplit5_kernel<<<dim3(Cv/64, Cv/64, 5), 256>>>(Wk, Wv, Wr, Wo, Wr2,
                                                   wkh, wvh, wrh, woh, wr2h);
    wsplit_kernel<<<dim3(Iv/64, Cv/64), 256>>>(Wk2, wk2h, Cv, Iv);  // [C,I] -> [I,C]
    wsplit_kernel<<<dim3(Cv/64, Iv/64), 256>>>(Wv2, wv2h, Iv, Cv);  // [I,C] -> [C,I]

    // --- time mixing ---
    fusedmix3_kernel<<<Mv, 256>>>(x, ln1_w, mk, mv, mr, xkh, xvh, xrh);
    hgemm_kvr<<<dim3(24, 128), 256, GSMEM>>>(xkh, xvh, xrh, wkh, wvh, wrh, ek, v, r);
    wkv_pass1<<<dim3(NCHUNK, Bv), Cv>>>(ek, v, td, sA, sB);
    wkv_pass2<<<Bv, Cv>>>(td, sA, sB);
    wkv_pass3<<<dim3(NCHUNK, Bv), Cv>>>(ek, v, r, td, tf, sA, sB, rwh);
    hgemm_add<<<dim3(8, 128), 256, GSMEM>>>(rwh, woh, x1, x);

    // --- channel mixing ---
    fusedmix2_kernel<<<Mv, 256>>>(x1, ln2_w, mk2, mr2, xkh, xrh);
    hgemm_k2r2<<<dim3(40, 128), 256, GSMEM>>>(xkh, xrh, wk2h, wr2h, k2h, r2);
    hgemm_muladd<<<dim3(8, 128), 256, GSMEM>>>(k2h, wv2h, out, x1, r2);
}